// round 2
// baseline (speedup 1.0000x reference)
#include <cuda_runtime.h>
#include <math.h>

#define TT 512
#define BB 256
#define IND 256
#define HH 512
#define OUTD 64
#define NBLK 128

// ---------------- device scratch (static allocations only) ----------------
__device__ float g_Wr[HH*HH];
__device__ float g_Wi[HH*HH];
__device__ float g_zre[BB*HH];
__device__ float g_zim[BB*HH];
__device__ float g_are[BB*HH];
__device__ float g_aim[BB*HH];
__device__ float g_amod[BB*HH];
__device__ float g_gre[BB*HH];
__device__ float g_gim[BB*HH];
__device__ float g_gtau[BB*HH];
__device__ float g_gux[BB*HH];
__device__ float g_bias_re[HH];
__device__ float g_bias_im[HH];
__device__ float g_partials[NBLK];
__device__ int            bar_cnt;      // zero-initialized; restored to 0 each barrier
__device__ volatile unsigned bar_gen;   // monotonically increasing generation

__device__ __forceinline__ float sigf(float v) { return 1.0f / (1.0f + expf(-v)); }
__device__ __forceinline__ float clampf(float v, float lo, float hi) {
    return fminf(hi, fmaxf(lo, v));
}

// Software grid barrier: all NBLK blocks are resident (NBLK <= 148 SMs, 1 CTA/SM).
__device__ __forceinline__ void grid_barrier() {
    __syncthreads();
    if (threadIdx.x == 0) {
        unsigned g = bar_gen;
        __threadfence();                      // release: make our writes visible
        if (atomicAdd(&bar_cnt, 1) == NBLK - 1) {
            bar_cnt = 0;
            __threadfence();
            bar_gen = g + 1;                  // release all spinners
        } else {
            while (bar_gen == g) { }          // spin (volatile load)
        }
        __threadfence();                      // acquire: see others' writes
    }
    __syncthreads();
}

__global__ void __launch_bounds__(256, 1)
twistor_persistent(const float* __restrict__ x,
                   const float* __restrict__ W_real_w, const float* __restrict__ W_real_b,
                   const float* __restrict__ W_imag_w, const float* __restrict__ W_imag_b,
                   const float* __restrict__ U_w,      const float* __restrict__ U_b,
                   const float* __restrict__ W_tau_w,  const float* __restrict__ W_tau_b,
                   const float* __restrict__ mask_real,const float* __restrict__ mask_imag,
                   const float* __restrict__ tau_bias,
                   const float* __restrict__ b_real,   const float* __restrict__ b_imag,
                   const float* __restrict__ out_w,    const float* __restrict__ out_b,
                   float* __restrict__ y)
{
    __shared__ float As[2][16][64];
    __shared__ float Bs[2][16][64];
    __shared__ float zsm[2][512];
    __shared__ float red[4][2][64];
    __shared__ float rbuf[8];
    __shared__ float warp_s[4];

    int tid = threadIdx.x;
    int bx  = blockIdx.x;

    // ---------------- prologue: masked weights, fused biases, state init ----
    for (int i = bx*256 + tid; i < HH*HH; i += NBLK*256) {
        g_Wr[i] = W_real_w[i] * sigf(mask_real[i]);
        g_Wi[i] = W_imag_w[i] * sigf(mask_imag[i]);
    }
    for (int i = bx*256 + tid; i < BB*HH; i += NBLK*256) {
        g_zre[i] = 0.0f; g_zim[i] = 0.0f;
        g_are[i] = 0.0f; g_aim[i] = 0.0f;
        g_amod[i] = 1e-6f;                    // sqrt(0+0+1e-12)
    }
    for (int i = bx*256 + tid; i < HH; i += NBLK*256) {
        g_bias_re[i] = W_real_b[i] + U_b[i] + b_real[i];
        g_bias_im[i] = W_imag_b[i] + U_b[i] + b_imag[i];
    }
    grid_barrier();

    // ---------------- per-block constant GEMM tile mapping -------------------
    int which = bx >> 5;            // 0:re  1:im  2:tau  3:Ux
    int tile  = bx & 31;
    int row0  = (tile >> 3) << 6;   // 0..192 over B=256
    int col0  = (tile & 7)  << 6;   // 0..448 over H=512

    const float* Abase; const float* W; float* C; int K;
    if      (which == 0) { Abase = g_are;  W = g_Wr;    C = g_gre;  K = HH;  }
    else if (which == 1) { Abase = g_aim;  W = g_Wi;    C = g_gim;  K = HH;  }
    else if (which == 2) { Abase = g_amod; W = W_tau_w; C = g_gtau; K = HH;  }
    else                 { Abase = x;      W = U_w;     C = g_gux;  K = IND; }

    int lr  = tid >> 2;             // 0..63
    int lk  = (tid & 3) << 2;       // 0,4,8,12
    int ty  = tid >> 4;             // 0..15
    int tx  = tid & 15;             // 0..15
    int NT  = K >> 4;

    const float4* Wg = (const float4*)(W + (size_t)(col0 + lr) * K + lk);

    for (int t = 0; t < TT; t++) {
        // ================= phase A: 4 fused GEMMs =================
        {
            const float* A = (which == 3) ? (Abase + (size_t)t*BB*IND) : Abase;
            const float4* Ag = (const float4*)(A + (size_t)(row0 + lr) * K + lk);

            float4 pa = Ag[0];
            float4 pw = Wg[0];
            As[0][lk+0][lr]=pa.x; As[0][lk+1][lr]=pa.y; As[0][lk+2][lr]=pa.z; As[0][lk+3][lr]=pa.w;
            Bs[0][lk+0][lr]=pw.x; Bs[0][lk+1][lr]=pw.y; Bs[0][lk+2][lr]=pw.z; Bs[0][lk+3][lr]=pw.w;
            __syncthreads();

            float acc[4][4];
            #pragma unroll
            for (int i = 0; i < 4; i++)
                #pragma unroll
                for (int j = 0; j < 4; j++) acc[i][j] = 0.0f;

            for (int jt = 0; jt < NT; ++jt) {
                int cur = jt & 1;
                if (jt + 1 < NT) { pa = Ag[(jt+1)*4]; pw = Wg[(jt+1)*4]; }
                #pragma unroll
                for (int k = 0; k < 16; ++k) {
                    float4 av = *(const float4*)&As[cur][k][ty*4];
                    float4 bv = *(const float4*)&Bs[cur][k][tx*4];
                    acc[0][0] += av.x*bv.x; acc[0][1] += av.x*bv.y; acc[0][2] += av.x*bv.z; acc[0][3] += av.x*bv.w;
                    acc[1][0] += av.y*bv.x; acc[1][1] += av.y*bv.y; acc[1][2] += av.y*bv.z; acc[1][3] += av.y*bv.w;
                    acc[2][0] += av.z*bv.x; acc[2][1] += av.z*bv.y; acc[2][2] += av.z*bv.z; acc[2][3] += av.z*bv.w;
                    acc[3][0] += av.w*bv.x; acc[3][1] += av.w*bv.y; acc[3][2] += av.w*bv.z; acc[3][3] += av.w*bv.w;
                }
                if (jt + 1 < NT) {
                    int nxt = cur ^ 1;
                    As[nxt][lk+0][lr]=pa.x; As[nxt][lk+1][lr]=pa.y; As[nxt][lk+2][lr]=pa.z; As[nxt][lk+3][lr]=pa.w;
                    Bs[nxt][lk+0][lr]=pw.x; Bs[nxt][lk+1][lr]=pw.y; Bs[nxt][lk+2][lr]=pw.z; Bs[nxt][lk+3][lr]=pw.w;
                    __syncthreads();
                }
            }

            #pragma unroll
            for (int i = 0; i < 4; i++) {
                float4 v = make_float4(acc[i][0], acc[i][1], acc[i][2], acc[i][3]);
                *(float4*)&C[(size_t)(row0 + ty*4 + i) * HH + col0 + tx*4] = v;
            }
        }
        grid_barrier();

        // ================= phase B1: elementwise + partial sums =================
        // Block bx owns rows [2*bx, 2*bx+2) of (B,H): 1024 floats = 256 float4.
        float dre[4], dimm[4], zreL[4], zimL[4];
        {
            int i4 = bx * 256 + tid;
            float4 vre = ((const float4*)g_gre)[i4];
            float4 vim = ((const float4*)g_gim)[i4];
            float4 vta = ((const float4*)g_gtau)[i4];
            float4 vux = ((const float4*)g_gux)[i4];
            float4 vzr = ((const float4*)g_zre)[i4];
            float4 vzi = ((const float4*)g_zim)[i4];
            int h0 = (i4 & 127) * 4;
            float4 vbr  = *(const float4*)&g_bias_re[h0];
            float4 vbi  = *(const float4*)&g_bias_im[h0];
            float4 vwtb = *(const float4*)&W_tau_b[h0];
            float4 vtb  = *(const float4*)&tau_bias[h0];

            float tre[4]  = {vre.x, vre.y, vre.z, vre.w};
            float tim[4]  = {vim.x, vim.y, vim.z, vim.w};
            float tta[4]  = {vta.x, vta.y, vta.z, vta.w};
            float tux[4]  = {vux.x, vux.y, vux.z, vux.w};
            float tzr[4]  = {vzr.x, vzr.y, vzr.z, vzr.w};
            float tzi[4]  = {vzi.x, vzi.y, vzi.z, vzi.w};
            float tbr[4]  = {vbr.x, vbr.y, vbr.z, vbr.w};
            float tbi[4]  = {vbi.x, vbi.y, vbi.z, vbi.w};
            float twtb[4] = {vwtb.x, vwtb.y, vwtb.z, vwtb.w};
            float ttb[4]  = {vtb.x, vtb.y, vtb.z, vtb.w};

            float lsum = 0.0f;
            #pragma unroll
            for (int j = 0; j < 4; j++) {
                float dzr = tre[j] + tux[j] + tbr[j] - tzr[j];
                float dzi = tim[j] + tux[j] + tbi[j] - tzi[j];
                float tau = clampf(sigf(tta[j] + twtb[j]) + ttb[j], 0.01f, 1.0f) + 1e-6f;
                float dr  = clampf(dzr / tau, -10.0f, 10.0f);
                float di  = clampf(dzi / tau, -10.0f, 10.0f);
                lsum += sqrtf(dr*dr + di*di + 1e-12f);
                dre[j] = dr;  dimm[j] = di;
                zreL[j] = tzr[j]; zimL[j] = tzi[j];
            }
            // fixed-order block reduce
            #pragma unroll
            for (int off = 16; off > 0; off >>= 1)
                lsum += __shfl_down_sync(0xFFFFFFFFu, lsum, off);
            if ((tid & 31) == 0) rbuf[tid >> 5] = lsum;
            __syncthreads();
            if (tid == 0) {
                float s = 0.0f;
                #pragma unroll
                for (int w = 0; w < 8; w++) s += rbuf[w];
                g_partials[bx] = s;
            }
        }
        grid_barrier();

        // ================= phase B2: scale (redundant, deterministic) + update ==
        {
            if (tid < 128) {
                float v = g_partials[tid];
                #pragma unroll
                for (int off = 16; off > 0; off >>= 1)
                    v += __shfl_down_sync(0xFFFFFFFFu, v, off);
                if ((tid & 31) == 0) warp_s[tid >> 5] = v;
            }
            __syncthreads();
            float tot  = ((warp_s[0] + warp_s[1]) + warp_s[2]) + warp_s[3];
            float mean = tot / (float)(BB * HH);
            float scale = (mean > 5.0f) ? (5.0f / (mean + 1e-6f)) : 1.0f;

            int i4 = bx * 256 + tid;
            float zr[4], zi[4], ar[4], ai[4], am[4];
            #pragma unroll
            for (int j = 0; j < 4; j++) {
                float znr = clampf(zreL[j] + 0.1f * scale * dre[j],  -100.0f, 100.0f);
                float zni = clampf(zimL[j] + 0.1f * scale * dimm[j], -100.0f, 100.0f);
                zr[j] = znr; zi[j] = zni;
                ar[j] = tanhf(znr); ai[j] = tanhf(zni);
                am[j] = sqrtf(znr*znr + zni*zni + 1e-12f);
            }
            float4 v;
            v = make_float4(zr[0],zr[1],zr[2],zr[3]);
            ((float4*)g_zre)[i4] = v;  ((float4*)zsm)[tid] = v;
            v = make_float4(zi[0],zi[1],zi[2],zi[3]); ((float4*)g_zim)[i4]  = v;
            v = make_float4(ar[0],ar[1],ar[2],ar[3]); ((float4*)g_are)[i4]  = v;
            v = make_float4(ai[0],ai[1],ai[2],ai[3]); ((float4*)g_aim)[i4]  = v;
            v = make_float4(am[0],am[1],am[2],am[3]); ((float4*)g_amod)[i4] = v;
            __syncthreads();

            // readout: y[t, 2bx + r, :] = zsm[r] @ out_w^T + out_b
            int o   = tid & 63;
            int seg = tid >> 6;                    // 0..3 : K-range [seg*128, +128)
            float acc0 = 0.0f, acc1 = 0.0f;
            const float4* wrow = (const float4*)(out_w + (size_t)o * 512 + seg * 128);
            #pragma unroll 8
            for (int k4 = 0; k4 < 32; k4++) {
                float4 w = wrow[k4];
                float4 z0 = *(const float4*)&zsm[0][seg*128 + k4*4];
                float4 z1 = *(const float4*)&zsm[1][seg*128 + k4*4];
                acc0 += w.x*z0.x + w.y*z0.y + w.z*z0.z + w.w*z0.w;
                acc1 += w.x*z1.x + w.y*z1.y + w.z*z1.z + w.w*z1.w;
            }
            red[seg][0][o] = acc0;
            red[seg][1][o] = acc1;
            __syncthreads();
            if (seg == 0) {
                float ob = out_b[o];
                #pragma unroll
                for (int r = 0; r < 2; r++) {
                    y[((size_t)t * BB + bx*2 + r) * OUTD + o] =
                        red[0][r][o] + red[1][r][o] + red[2][r][o] + red[3][r][o] + ob;
                }
            }
        }
        grid_barrier();
    }
}

// ---------------- host launcher (graph-capturable, single node) -------------
extern "C" void kernel_launch(void* const* d_in, const int* in_sizes, int n_in,
                              void* d_out, int out_size)
{
    const float* x         = (const float*)d_in[0];
    const float* W_real_w  = (const float*)d_in[1];
    const float* W_real_b  = (const float*)d_in[2];
    const float* W_imag_w  = (const float*)d_in[3];
    const float* W_imag_b  = (const float*)d_in[4];
    const float* U_w       = (const float*)d_in[5];
    const float* U_b       = (const float*)d_in[6];
    const float* W_tau_w   = (const float*)d_in[7];
    const float* W_tau_b   = (const float*)d_in[8];
    const float* mask_real = (const float*)d_in[9];
    const float* mask_imag = (const float*)d_in[10];
    const float* tau_bias  = (const float*)d_in[11];
    const float* b_real    = (const float*)d_in[12];
    const float* b_imag    = (const float*)d_in[13];
    const float* out_w     = (const float*)d_in[14];
    const float* out_b     = (const float*)d_in[15];
    float* y = (float*)d_out;

    twistor_persistent<<<NBLK, 256>>>(x, W_real_w, W_real_b, W_imag_w, W_imag_b,
                                      U_w, U_b, W_tau_w, W_tau_b,
                                      mask_real, mask_imag, tau_bias,
                                      b_real, b_imag, out_w, out_b, y);
}

// round 6
// speedup vs baseline: 1.0936x; 1.0936x over previous
#include <cuda_runtime.h>
#include <cuda_bf16.h>
#include <mma.h>
#include <math.h>

using namespace nvcuda;

#define TT 512
#define BB 256
#define IND 256
#define HH 512
#define OUTD 64
#define NBLK 128

// ---------------- device scratch (static allocations only) ----------------
// Stacked split-bf16 weights, per row layout: [hi(512) | lo(512) | hi(512)]
__device__ __nv_bfloat16 g_Wsre[HH*1536];
__device__ __nv_bfloat16 g_Wsim[HH*1536];
__device__ __nv_bfloat16 g_Wstau[HH*1536];
__device__ __nv_bfloat16 g_Us[HH*768];
__device__ __nv_bfloat16 g_Xs[(size_t)TT*BB*512];
// Split-bf16 activations, per row layout: [hi(512) | lo(512)]
__device__ __nv_bfloat16 g_Are[BB*1024];
__device__ __nv_bfloat16 g_Aim[BB*1024];
__device__ __nv_bfloat16 g_Amod[BB*1024];
__device__ float g_zre[BB*HH];
__device__ float g_zim[BB*HH];
__device__ float g_gre[BB*HH];
__device__ float g_gim[BB*HH];
__device__ float g_gtau[BB*HH];
__device__ float g_gux[BB*HH];
__device__ float g_bias_re[HH];
__device__ float g_bias_im[HH];
__device__ float g_partials[NBLK];
__device__ int bar_cnt;
__device__ volatile unsigned bar_gen;

__device__ __forceinline__ float sigf(float v) { return 1.0f / (1.0f + expf(-v)); }

__device__ __forceinline__ float clampf(float v, float lo, float hi) {
    return fminf(hi, fmaxf(lo, v));
}

// Software grid barrier: all NBLK blocks resident (128 under 148 SMs, 1 CTA/SM).
__device__ __forceinline__ void grid_barrier() {
    __syncthreads();
    if (threadIdx.x == 0) {
        unsigned g = bar_gen;
        __threadfence();
        if (atomicAdd(&bar_cnt, 1) == NBLK - 1) {
            bar_cnt = 0;
            __threadfence();
            bar_gen = g + 1;
        } else {
            while (bar_gen == g) { }
        }
        __threadfence();
    }
    __syncthreads();
}

__global__ void __launch_bounds__(256, 1)
twistor_persistent(const float* __restrict__ x,
                   const float* __restrict__ W_real_w, const float* __restrict__ W_real_b,
                   const float* __restrict__ W_imag_w, const float* __restrict__ W_imag_b,
                   const float* __restrict__ U_w,      const float* __restrict__ U_b,
                   const float* __restrict__ W_tau_w,  const float* __restrict__ W_tau_b,
                   const float* __restrict__ mask_real,const float* __restrict__ mask_imag,
                   const float* __restrict__ tau_bias,
                   const float* __restrict__ b_real,   const float* __restrict__ b_imag,
                   const float* __restrict__ out_w,    const float* __restrict__ out_b,
                   float* __restrict__ y)
{
    __shared__ __nv_bfloat16 sA[2][64*72];
    __shared__ __nv_bfloat16 sB[2][64*72];
    __shared__ float zsm[2][512];
    __shared__ float red[4][2][64];
    __shared__ float rbuf[8];
    __shared__ float warp_s[4];

    int tid = threadIdx.x;
    int bx  = blockIdx.x;
    int gtid = bx*256 + tid;
    const int NTOT = NBLK*256;

    // ---------------- prologue ------------------------------------------
    for (int i = gtid; i < HH*HH; i += NTOT) {
        int rr = i >> 9;
        int cc = i & 511;
        int base = rr*1536 + cc;
        float wv;
        float hv;
        __nv_bfloat16 hb;
        __nv_bfloat16 lb;
        wv = W_real_w[i] * sigf(mask_real[i]);
        hb = __float2bfloat16_rn(wv);
        hv = __bfloat162float(hb);
        lb = __float2bfloat16_rn(wv - hv);
        g_Wsre[base] = hb;
        g_Wsre[base+512] = lb;
        g_Wsre[base+1024] = hb;
        wv = W_imag_w[i] * sigf(mask_imag[i]);
        hb = __float2bfloat16_rn(wv);
        hv = __bfloat162float(hb);
        lb = __float2bfloat16_rn(wv - hv);
        g_Wsim[base] = hb;
        g_Wsim[base+512] = lb;
        g_Wsim[base+1024] = hb;
        wv = W_tau_w[i];
        hb = __float2bfloat16_rn(wv);
        hv = __bfloat162float(hb);
        lb = __float2bfloat16_rn(wv - hv);
        g_Wstau[base] = hb;
        g_Wstau[base+512] = lb;
        g_Wstau[base+1024] = hb;
    }
    for (int i = gtid; i < HH*IND; i += NTOT) {
        int rr = i >> 8;
        int cc = i & 255;
        int base = rr*768 + cc;
        float wv = U_w[i];
        __nv_bfloat16 hb = __float2bfloat16_rn(wv);
        float hv = __bfloat162float(hb);
        __nv_bfloat16 lb = __float2bfloat16_rn(wv - hv);
        g_Us[base] = hb;
        g_Us[base+256] = lb;
        g_Us[base+512] = hb;
    }
    for (size_t i = gtid; i < (size_t)TT*BB*IND; i += NTOT) {
        size_t rr = i >> 8;
        int cc = (int)(i & 255);
        float wv = x[i];
        __nv_bfloat16 hb = __float2bfloat16_rn(wv);
        float hv = __bfloat162float(hb);
        __nv_bfloat16 lb = __float2bfloat16_rn(wv - hv);
        g_Xs[rr*512 + cc] = hb;
        g_Xs[rr*512 + 256 + cc] = lb;
    }
    {
        __nv_bfloat16 mh = __float2bfloat16_rn(1e-6f);
        float mhv = __bfloat162float(mh);
        __nv_bfloat16 ml = __float2bfloat16_rn(1e-6f - mhv);
        __nv_bfloat16 zb = __float2bfloat16_rn(0.0f);
        for (int i = gtid; i < BB*HH; i += NTOT) {
            int rr = i >> 9;
            int cc = i & 511;
            g_zre[i] = 0.0f;
            g_zim[i] = 0.0f;
            g_Are[rr*1024+cc] = zb;
            g_Are[rr*1024+512+cc] = zb;
            g_Aim[rr*1024+cc] = zb;
            g_Aim[rr*1024+512+cc] = zb;
            g_Amod[rr*1024+cc] = mh;
            g_Amod[rr*1024+512+cc] = ml;
        }
    }
    for (int i = gtid; i < HH; i += NTOT) {
        g_bias_re[i] = W_real_b[i] + U_b[i] + b_real[i];
        g_bias_im[i] = W_imag_b[i] + U_b[i] + b_imag[i];
    }
    grid_barrier();

    // ---------------- per-block GEMM tile mapping ------------------------
    int which = bx >> 5;
    int tile  = bx & 31;
    int m0    = (tile >> 3) << 6;
    int n0    = (tile & 7)  << 6;

    const __nv_bfloat16* Abase;
    const __nv_bfloat16* Wg;
    float* C;
    int KP;
    int RSA;
    int RSW;
    if (which == 0) {
        Abase = g_Are;  Wg = g_Wsre;  C = g_gre;  KP = 1536; RSA = 1024; RSW = 1536;
    } else if (which == 1) {
        Abase = g_Aim;  Wg = g_Wsim;  C = g_gim;  KP = 1536; RSA = 1024; RSW = 1536;
    } else if (which == 2) {
        Abase = g_Amod; Wg = g_Wstau; C = g_gtau; KP = 1536; RSA = 1024; RSW = 1536;
    } else {
        Abase = g_Xs;   Wg = g_Us;    C = g_gux;  KP = 768;  RSA = 512;  RSW = 768;
    }
    int NC = KP >> 6;

    int lr  = tid >> 3;
    int lc8 = (tid & 7) * 8;
    int wid = tid >> 5;
    int wm  = wid & 3;        // m tile index, 16 rows each
    int wnp = wid >> 2;       // n pair index, covers 2 n-tiles of 16 cols

    for (int t = 0; t < TT; t++) {
        // ================= phase A: split-bf16 wmma GEMMs ==================
        {
            const __nv_bfloat16* Ag = Abase;
            if (which == 3) {
                Ag = g_Xs + (size_t)t*BB*512;
            }

            wmma::fragment<wmma::accumulator, 16, 16, 16, float> acc0;
            wmma::fragment<wmma::accumulator, 16, 16, 16, float> acc1;
            wmma::fill_fragment(acc0, 0.0f);
            wmma::fill_fragment(acc1, 0.0f);

            uint4 ra0 = *(const uint4*)(Ag + (size_t)(m0+lr   )*RSA + lc8);
            uint4 ra1 = *(const uint4*)(Ag + (size_t)(m0+lr+32)*RSA + lc8);
            uint4 rb0 = *(const uint4*)(Wg + (size_t)(n0+lr   )*RSW + lc8);
            uint4 rb1 = *(const uint4*)(Wg + (size_t)(n0+lr+32)*RSW + lc8);
            *(uint4*)(&sA[0][lr*72      + lc8]) = ra0;
            *(uint4*)(&sA[0][(lr+32)*72 + lc8]) = ra1;
            *(uint4*)(&sB[0][lr*72      + lc8]) = rb0;
            *(uint4*)(&sB[0][(lr+32)*72 + lc8]) = rb1;
            __syncthreads();

            for (int ch = 0; ch < NC; ch++) {
                int cur = ch & 1;
                if (ch + 1 < NC) {
                    int kc = (ch + 1) << 6;
                    int ac;
                    if (which == 3) {
                        if (kc < 512) { ac = kc & 255; } else { ac = kc - 256; }
                    } else {
                        if (kc < 1024) { ac = kc & 511; } else { ac = kc - 512; }
                    }
                    ra0 = *(const uint4*)(Ag + (size_t)(m0+lr   )*RSA + ac + lc8);
                    ra1 = *(const uint4*)(Ag + (size_t)(m0+lr+32)*RSA + ac + lc8);
                    rb0 = *(const uint4*)(Wg + (size_t)(n0+lr   )*RSW + kc + lc8);
                    rb1 = *(const uint4*)(Wg + (size_t)(n0+lr+32)*RSW + kc + lc8);
                }
                const __nv_bfloat16* sAc = &sA[cur][0];
                const __nv_bfloat16* sBc = &sB[cur][0];
                #pragma unroll
                for (int q = 0; q < 4; q++) {
                    wmma::fragment<wmma::matrix_a, 16, 16, 16, __nv_bfloat16, wmma::row_major> fa;
                    wmma::fragment<wmma::matrix_b, 16, 16, 16, __nv_bfloat16, wmma::col_major> fb0;
                    wmma::fragment<wmma::matrix_b, 16, 16, 16, __nv_bfloat16, wmma::col_major> fb1;
                    wmma::load_matrix_sync(fa,  sAc + (wm*16)*72 + q*16, 72);
                    wmma::load_matrix_sync(fb0, sBc + (wnp*32)*72 + q*16, 72);
                    wmma::load_matrix_sync(fb1, sBc + (wnp*32+16)*72 + q*16, 72);
                    wmma::mma_sync(acc0, fa, fb0, acc0);
                    wmma::mma_sync(acc1, fa, fb1, acc1);
                }
                if (ch + 1 < NC) {
                    int nxt = cur ^ 1;
                    __nv_bfloat16* dA = &sA[nxt][0];
                    __nv_bfloat16* dB = &sB[nxt][0];
                    *(uint4*)(dA + lr*72      + lc8) = ra0;
                    *(uint4*)(dA + (lr+32)*72 + lc8) = ra1;
                    *(uint4*)(dB + lr*72      + lc8) = rb0;
                    *(uint4*)(dB + (lr+32)*72 + lc8) = rb1;
                    __syncthreads();
                }
            }

            float* Cout = C + (size_t)(m0 + wm*16)*512 + n0 + wnp*32;
            wmma::store_matrix_sync(Cout,      acc0, 512, wmma::mem_row_major);
            wmma::store_matrix_sync(Cout + 16, acc1, 512, wmma::mem_row_major);
        }
        grid_barrier();

        // ================= phase B1: elementwise + partial sums =============
        float dre[4];
        float dimm[4];
        float zreL[4];
        float zimL[4];
        {
            int i4 = bx * 256 + tid;
            float4 vre = ((const float4*)g_gre)[i4];
            float4 vim = ((const float4*)g_gim)[i4];
            float4 vta = ((const float4*)g_gtau)[i4];
            float4 vux = ((const float4*)g_gux)[i4];
            float4 vzr = ((const float4*)g_zre)[i4];
            float4 vzi = ((const float4*)g_zim)[i4];
            int h0 = (i4 & 127) * 4;
            float4 vbr  = *(const float4*)(&g_bias_re[h0]);
            float4 vbi  = *(const float4*)(&g_bias_im[h0]);
            float4 vwtb = *(const float4*)(&W_tau_b[h0]);
            float4 vtb  = *(const float4*)(&tau_bias[h0]);

            float tre[4];
            float tim[4];
            float tta[4];
            float tux[4];
            float tzr[4];
            float tzi[4];
            float tbr[4];
            float tbi[4];
            float twtb[4];
            float ttb[4];
            tre[0] = vre.x; tre[1] = vre.y; tre[2] = vre.z; tre[3] = vre.w;
            tim[0] = vim.x; tim[1] = vim.y; tim[2] = vim.z; tim[3] = vim.w;
            tta[0] = vta.x; tta[1] = vta.y; tta[2] = vta.z; tta[3] = vta.w;
            tux[0] = vux.x; tux[1] = vux.y; tux[2] = vux.z; tux[3] = vux.w;
            tzr[0] = vzr.x; tzr[1] = vzr.y; tzr[2] = vzr.z; tzr[3] = vzr.w;
            tzi[0] = vzi.x; tzi[1] = vzi.y; tzi[2] = vzi.z; tzi[3] = vzi.w;
            tbr[0] = vbr.x; tbr[1] = vbr.y; tbr[2] = vbr.z; tbr[3] = vbr.w;
            tbi[0] = vbi.x; tbi[1] = vbi.y; tbi[2] = vbi.z; tbi[3] = vbi.w;
            twtb[0] = vwtb.x; twtb[1] = vwtb.y; twtb[2] = vwtb.z; twtb[3] = vwtb.w;
            ttb[0] = vtb.x; ttb[1] = vtb.y; ttb[2] = vtb.z; ttb[3] = vtb.w;

            float lsum = 0.0f;
            #pragma unroll
            for (int j = 0; j < 4; j++) {
                float dzr = tre[j] + tux[j] + tbr[j] - tzr[j];
                float dzi = tim[j] + tux[j] + tbi[j] - tzi[j];
                float tau = clampf(sigf(tta[j] + twtb[j]) + ttb[j], 0.01f, 1.0f) + 1e-6f;
                float dr  = clampf(dzr / tau, -10.0f, 10.0f);
                float di  = clampf(dzi / tau, -10.0f, 10.0f);
                lsum += sqrtf(dr*dr + di*di + 1e-12f);
                dre[j] = dr;
                dimm[j] = di;
                zreL[j] = tzr[j];
                zimL[j] = tzi[j];
            }
            #pragma unroll
            for (int off = 16; off > 0; off >>= 1) {
                lsum += __shfl_down_sync(0xFFFFFFFFu, lsum, off);
            }
            if ((tid & 31) == 0) {
                rbuf[tid >> 5] = lsum;
            }
            __syncthreads();
            if (tid == 0) {
                float s = 0.0f;
                #pragma unroll
                for (int ww = 0; ww < 8; ww++) {
                    s += rbuf[ww];
                }
                g_partials[bx] = s;
            }
        }
        grid_barrier();

        // ================= phase B2: scale + update + readout ===============
        {
            if (tid < 128) {
                float pv = g_partials[tid];
                #pragma unroll
                for (int off = 16; off > 0; off >>= 1) {
                    pv += __shfl_down_sync(0xFFFFFFFFu, pv, off);
                }
                if ((tid & 31) == 0) {
                    warp_s[tid >> 5] = pv;
                }
            }
            __syncthreads();
            float tot  = ((warp_s[0] + warp_s[1]) + warp_s[2]) + warp_s[3];
            float mean = tot / (float)(BB * HH);
            float scale = 1.0f;
            if (mean > 5.0f) {
                scale = 5.0f / (mean + 1e-6f);
            }

            int i4 = bx * 256 + tid;
            int flat0 = i4 * 4;
            int arow  = flat0 >> 9;
            int acol  = flat0 & 511;
            int abase = arow*1024 + acol;

            float zrA[4];
            float ziA[4];
            #pragma unroll
            for (int j = 0; j < 4; j++) {
                float znr = clampf(zreL[j] + 0.1f * scale * dre[j],  -100.0f, 100.0f);
                float zni = clampf(zimL[j] + 0.1f * scale * dimm[j], -100.0f, 100.0f);
                zrA[j] = znr;
                ziA[j] = zni;
                float arv = tanhf(znr);
                float aiv = tanhf(zni);
                float amv = sqrtf(znr*znr + zni*zni + 1e-12f);
                __nv_bfloat16 hb;
                float hv;
                hb = __float2bfloat16_rn(arv);
                hv = __bfloat162float(hb);
                g_Are[abase+j] = hb;
                g_Are[abase+512+j] = __float2bfloat16_rn(arv - hv);
                hb = __float2bfloat16_rn(aiv);
                hv = __bfloat162float(hb);
                g_Aim[abase+j] = hb;
                g_Aim[abase+512+j] = __float2bfloat16_rn(aiv - hv);
                hb = __float2bfloat16_rn(amv);
                hv = __bfloat162float(hb);
                g_Amod[abase+j] = hb;
                g_Amod[abase+512+j] = __float2bfloat16_rn(amv - hv);
            }
            float4 vout;
            vout = make_float4(zrA[0], zrA[1], zrA[2], zrA[3]);
            ((float4*)g_zre)[i4] = vout;
            ((float4*)(&zsm[0][0]))[tid] = vout;
            vout = make_float4(ziA[0], ziA[1], ziA[2], ziA[3]);
            ((float4*)g_zim)[i4] = vout;
            __syncthreads();

            // readout: y[t, 2bx + r, :] = zsm[r] times out_w transpose + out_b
            int o   = tid & 63;
            int seg = tid >> 6;
            float acc0 = 0.0f;
            float acc1 = 0.0f;
            const float4* wrow = (const float4*)(out_w + (size_t)o * 512 + seg * 128);
            #pragma unroll 8
            for (int k4 = 0; k4 < 32; k4++) {
                float4 wv = wrow[k4];
                float4 z0 = *(const float4*)(&zsm[0][seg*128 + k4*4]);
                float4 z1 = *(const float4*)(&zsm[1][seg*128 + k4*4]);
                acc0 += wv.x*z0.x + wv.y*z0.y + wv.z*z0.z + wv.w*z0.w;
                acc1 += wv.x*z1.x + wv.y*z1.y + wv.z*z1.z + wv.w*z1.w;
            }
            red[seg][0][o] = acc0;
            red[seg][1][o] = acc1;
            __syncthreads();
            if (seg == 0) {
                float ob = out_b[o];
                #pragma unroll
                for (int r = 0; r < 2; r++) {
                    float yv = red[0][r][o] + red[1][r][o] + red[2][r][o] + red[3][r][o] + ob;
                    y[((size_t)t * BB + bx*2 + r) * OUTD + o] = yv;
                }
            }
        }
        grid_barrier();
    }
}

// ---------------- host launcher (graph-capturable, single node) ------------
extern "C" void kernel_launch(void* const* d_in, const int* in_sizes, int n_in,
                              void* d_out, int out_size)
{
    const float* x         = (const float*)d_in[0];
    const float* W_real_w  = (const float*)d_in[1];
    const float* W_real_b  = (const float*)d_in[2];
    const float* W_imag_w  = (const float*)d_in[3];
    const float* W_imag_b  = (const float*)d_in[4];
    const float* U_w       = (const float*)d_in[5];
    const float* U_b       = (const float*)d_in[6];
    const float* W_tau_w   = (const float*)d_in[7];
    const float* W_tau_b   = (const float*)d_in[8];
    const float* mask_real = (const float*)d_in[9];
    const float* mask_imag = (const float*)d_in[10];
    const float* tau_bias  = (const float*)d_in[11];
    const float* b_real    = (const float*)d_in[12];
    const float* b_imag    = (const float*)d_in[13];
    const float* out_w     = (const float*)d_in[14];
    const float* out_b     = (const float*)d_in[15];
    float* y = (float*)d_out;

    twistor_persistent<<<NBLK, 256>>>(x, W_real_w, W_real_b, W_imag_w, W_imag_b,
                                      U_w, U_b, W_tau_w, W_tau_b,
                                      mask_real, mask_imag, tau_bias,
                                      b_real, b_imag, out_w, out_b, y);
}